// round 5
// baseline (speedup 1.0000x reference)
#include <cuda_runtime.h>
#include <cstdint>

#define HW_ (128*128)
#define NTOT (16*64)

__device__ float g_Q[NTOT * HW_];
__device__ float g_V[NTOT * HW_];
__device__ float g_K[NTOT * HW_];

// ---------------------------------------------------------------------------
// Kernel 1: fused 1x1-conv projections (R1 scalar version — measured fastest).
// ---------------------------------------------------------------------------
__global__ __launch_bounds__(256) void qvk_kernel(
    const float* __restrict__ x, const float* __restrict__ e,
    const float* __restrict__ W1, const float* __restrict__ b1,
    const float* __restrict__ W2, const float* __restrict__ b2,
    const float* __restrict__ W3, const float* __restrict__ b3)
{
    extern __shared__ float sm[];
    float* Xs  = sm;               // [64][128]
    float* Es  = Xs + 64*128;      // [16][128]
    float* W2s = Es + 16*128;      // [64][68]
    float* W3s = W2s + 64*68;
    float* W1s = W3s + 64*68;      // [16][68]
    float* b1s = W1s + 16*68;
    float* b2s = b1s + 64;
    float* b3s = b2s + 64;

    const int tid = threadIdx.x;
    const int b   = blockIdx.y;
    const int p0  = blockIdx.x * 128;

    for (int idx = tid; idx < 4096; idx += 256) {
        int o = idx >> 6, c = idx & 63;
        W2s[c*68 + o] = W2[idx];
        W3s[c*68 + o] = W3[idx];
    }
    for (int idx = tid; idx < 1024; idx += 256) {
        int o = idx >> 4, c = idx & 15;
        W1s[c*68 + o] = W1[idx];
    }
    if (tid < 64) { b1s[tid] = b1[tid]; b2s[tid] = b2[tid]; b3s[tid] = b3[tid]; }

    for (int idx = tid; idx < 64*128; idx += 256) {
        int c = idx >> 7, p = idx & 127;
        Xs[idx] = x[(b*64 + c)*HW_ + p0 + p];
    }
    for (int idx = tid; idx < 16*128; idx += 256) {
        int c = idx >> 7, p = idx & 127;
        Es[idx] = e[(b*16 + c)*HW_ + p0 + p];
    }
    __syncthreads();

    const int oi = tid >> 4;
    const int pj = tid & 15;

    float accQ[4][8], accV[4][8], accK[4][8];
    #pragma unroll
    for (int i = 0; i < 4; i++) {
        float bq = b1s[oi*4+i], bv = b2s[oi*4+i], bk = b3s[oi*4+i];
        #pragma unroll
        for (int j = 0; j < 8; j++) { accQ[i][j] = bq; accV[i][j] = bv; accK[i][j] = bk; }
    }

    #pragma unroll 4
    for (int c = 0; c < 64; c++) {
        float4 a2v = *(const float4*)&W2s[c*68 + oi*4];
        float4 a3v = *(const float4*)&W3s[c*68 + oi*4];
        float4 x0  = *(const float4*)&Xs[c*128 + pj*8];
        float4 x1  = *(const float4*)&Xs[c*128 + pj*8 + 4];
        float av2[4] = {a2v.x, a2v.y, a2v.z, a2v.w};
        float av3[4] = {a3v.x, a3v.y, a3v.z, a3v.w};
        float xv[8]  = {x0.x, x0.y, x0.z, x0.w, x1.x, x1.y, x1.z, x1.w};
        #pragma unroll
        for (int i = 0; i < 4; i++)
            #pragma unroll
            for (int j = 0; j < 8; j++) {
                accV[i][j] += av2[i] * xv[j];
                accK[i][j] += av3[i] * xv[j];
            }
    }
    #pragma unroll 4
    for (int c = 0; c < 16; c++) {
        float4 a1v = *(const float4*)&W1s[c*68 + oi*4];
        float4 e0  = *(const float4*)&Es[c*128 + pj*8];
        float4 e1  = *(const float4*)&Es[c*128 + pj*8 + 4];
        float av1[4] = {a1v.x, a1v.y, a1v.z, a1v.w};
        float ev[8]  = {e0.x, e0.y, e0.z, e0.w, e1.x, e1.y, e1.z, e1.w};
        #pragma unroll
        for (int i = 0; i < 4; i++)
            #pragma unroll
            for (int j = 0; j < 8; j++)
                accQ[i][j] += av1[i] * ev[j];
    }

    #pragma unroll
    for (int i = 0; i < 4; i++) {
        int o  = oi*4 + i;
        int gb = (b*64 + o)*HW_ + p0 + pj*8;
        *(float4*)&g_Q[gb]     = make_float4(accQ[i][0], accQ[i][1], accQ[i][2], accQ[i][3]);
        *(float4*)&g_Q[gb + 4] = make_float4(accQ[i][4], accQ[i][5], accQ[i][6], accQ[i][7]);
        *(float4*)&g_V[gb]     = make_float4(accV[i][0], accV[i][1], accV[i][2], accV[i][3]);
        *(float4*)&g_V[gb + 4] = make_float4(accV[i][4], accV[i][5], accV[i][6], accV[i][7]);
        *(float4*)&g_K[gb]     = make_float4(accK[i][0], accK[i][1], accK[i][2], accK[i][3]);
        *(float4*)&g_K[gb + 4] = make_float4(accK[i][4], accK[i][5], accK[i][6], accK[i][7]);
    }
}

// ---------------------------------------------------------------------------
// Kernel 2: per-head attention on tensor cores (tf32 mma, 3-term split).
// B operand (V then K) pre-split into interleaved (hi,lo) pairs in smem.
// One CTA (8 warps, 256 thr) per head. Warp w owns output rows [w*16, w*16+16).
// ---------------------------------------------------------------------------
#define LDA 132
#define LDB 264   // floats per B row: 128 (hi,lo) pairs + 8 pad

__device__ __forceinline__ void mma_tf32(float c[4], const uint32_t a[4],
                                         const uint32_t b0, const uint32_t b1) {
    asm volatile(
        "mma.sync.aligned.m16n8k8.row.col.f32.tf32.tf32.f32 "
        "{%0,%1,%2,%3}, {%4,%5,%6,%7}, {%8,%9}, {%0,%1,%2,%3};"
        : "+f"(c[0]), "+f"(c[1]), "+f"(c[2]), "+f"(c[3])
        : "r"(a[0]), "r"(a[1]), "r"(a[2]), "r"(a[3]), "r"(b0), "r"(b1));
}

__device__ __forceinline__ void tf32_split(float x, uint32_t& hi, uint32_t& lo) {
    hi = __float_as_uint(x) & 0xffffe000u;
    float r = x - __uint_as_float(hi);
    lo = __float_as_uint(r) & 0xffffe000u;
}

__global__ __launch_bounds__(256) void attn_kernel(float* __restrict__ out)
{
    extern __shared__ float sm[];
    float* A  = sm;              // Q[h][w] (plain) -> later P[h][g]
    float* Bs = sm + 128*LDA;    // (hi,lo) pairs: V[g][w] -> later K[g][w]

    const int tid  = threadIdx.x;
    const int warp = tid >> 5;
    const int lane = tid & 31;
    const int n    = blockIdx.x;
    const float* Q = g_Q + n*HW_;
    const float* V = g_V + n*HW_;
    const float* K = g_K + n*HW_;

    // Stage Q plain; V pre-split into (hi,lo) pairs
    for (int idx = tid; idx < HW_; idx += 256) {
        int row = idx >> 7, col = idx & 127;
        A[row*LDA + col] = Q[idx];
        uint32_t hi, lo;
        tf32_split(V[idx], hi, lo);
        *(float2*)&Bs[row*LDB + col*2] =
            make_float2(__uint_as_float(hi), __uint_as_float(lo));
    }
    __syncthreads();

    const int g4 = lane >> 2;        // 0..7
    const int tg = lane & 3;         // 0..3
    const int r0 = warp*16 + g4;     // rows r0 (c0/c1) and r0+8 (c2/c3)

    float acc[16][4];
    #pragma unroll
    for (int nt = 0; nt < 16; nt++)
        #pragma unroll
        for (int i = 0; i < 4; i++) acc[nt][i] = 0.0f;

    // ---- Phase A: S = Q @ V^T.  B[k][nn] = V[nn][k] (col-major fragment)
    #pragma unroll 1
    for (int k = 0; k < 16; k++) {
        const int kb = k*8 + tg;
        uint32_t ah[4], al[4];
        tf32_split(A[r0*LDA + kb],         ah[0], al[0]);
        tf32_split(A[(r0+8)*LDA + kb],     ah[1], al[1]);
        tf32_split(A[r0*LDA + kb + 4],     ah[2], al[2]);
        tf32_split(A[(r0+8)*LDA + kb + 4], ah[3], al[3]);
        #pragma unroll
        for (int nt = 0; nt < 16; nt++) {
            const int gc = nt*8 + g4;
            float2 b0 = *(const float2*)&Bs[gc*LDB + kb*2];
            float2 b1 = *(const float2*)&Bs[gc*LDB + (kb+4)*2];
            uint32_t bh0 = __float_as_uint(b0.x), bl0 = __float_as_uint(b0.y);
            uint32_t bh1 = __float_as_uint(b1.x), bl1 = __float_as_uint(b1.y);
            mma_tf32(acc[nt], ah, bh0, bh1);
            mma_tf32(acc[nt], al, bh0, bh1);
            mma_tf32(acc[nt], ah, bl0, bl1);
        }
    }

    // ---- Softmax over columns (rows r0, r0+8 live in this thread-quad)
    float m1 = -1e30f, m2 = -1e30f;
    #pragma unroll
    for (int nt = 0; nt < 16; nt++) {
        m1 = fmaxf(m1, fmaxf(acc[nt][0], acc[nt][1]));
        m2 = fmaxf(m2, fmaxf(acc[nt][2], acc[nt][3]));
    }
    #pragma unroll
    for (int off = 1; off < 4; off <<= 1) {
        m1 = fmaxf(m1, __shfl_xor_sync(0xFFFFFFFFu, m1, off));
        m2 = fmaxf(m2, __shfl_xor_sync(0xFFFFFFFFu, m2, off));
    }
    float s1 = 0.0f, s2 = 0.0f;
    #pragma unroll
    for (int nt = 0; nt < 16; nt++) {
        acc[nt][0] = __expf(acc[nt][0] - m1);
        acc[nt][1] = __expf(acc[nt][1] - m1);
        acc[nt][2] = __expf(acc[nt][2] - m2);
        acc[nt][3] = __expf(acc[nt][3] - m2);
        s1 += acc[nt][0] + acc[nt][1];
        s2 += acc[nt][2] + acc[nt][3];
    }
    #pragma unroll
    for (int off = 1; off < 4; off <<= 1) {
        s1 += __shfl_xor_sync(0xFFFFFFFFu, s1, off);
        s2 += __shfl_xor_sync(0xFFFFFFFFu, s2, off);
    }
    const float inv1 = 1.0f / s1, inv2 = 1.0f / s2;

    // Store unnormalized P into A (warp-private 16-row band; Q there is dead)
    #pragma unroll
    for (int nt = 0; nt < 16; nt++) {
        *(float2*)&A[r0*LDA     + nt*8 + 2*tg] = make_float2(acc[nt][0], acc[nt][1]);
        *(float2*)&A[(r0+8)*LDA + nt*8 + 2*tg] = make_float2(acc[nt][2], acc[nt][3]);
    }
    __syncthreads();   // all warps done reading V from Bs

    // Stage K pre-split (k-major rows: Bs[g][w] pairs)
    for (int idx = tid; idx < HW_; idx += 256) {
        int row = idx >> 7, col = idx & 127;
        uint32_t hi, lo;
        tf32_split(K[idx], hi, lo);
        *(float2*)&Bs[row*LDB + col*2] =
            make_float2(__uint_as_float(hi), __uint_as_float(lo));
    }
    __syncthreads();

    // ---- Phase C: ctx = P @ K.  B[k][nn] = K[k][nn]
    float oac[16][4];
    #pragma unroll
    for (int nt = 0; nt < 16; nt++)
        #pragma unroll
        for (int i = 0; i < 4; i++) oac[nt][i] = 0.0f;

    #pragma unroll 1
    for (int k = 0; k < 16; k++) {
        const int kb = k*8 + tg;
        uint32_t ah[4], al[4];
        tf32_split(A[r0*LDA + kb],         ah[0], al[0]);
        tf32_split(A[(r0+8)*LDA + kb],     ah[1], al[1]);
        tf32_split(A[r0*LDA + kb + 4],     ah[2], al[2]);
        tf32_split(A[(r0+8)*LDA + kb + 4], ah[3], al[3]);
        #pragma unroll
        for (int nt = 0; nt < 16; nt++) {
            const int nc = nt*8 + g4;
            float2 b0 = *(const float2*)&Bs[kb*LDB + nc*2];
            float2 b1 = *(const float2*)&Bs[(kb+4)*LDB + nc*2];
            uint32_t bh0 = __float_as_uint(b0.x), bl0 = __float_as_uint(b0.y);
            uint32_t bh1 = __float_as_uint(b1.x), bl1 = __float_as_uint(b1.y);
            mma_tf32(oac[nt], ah, bh0, bh1);
            mma_tf32(oac[nt], al, bh0, bh1);
            mma_tf32(oac[nt], ah, bl0, bl1);
        }
    }

    // Epilogue: scale rows by 1/rowsum, write out
    #pragma unroll
    for (int nt = 0; nt < 16; nt++) {
        int cbase = nt*8 + 2*tg;
        *(float2*)&out[n*HW_ + r0*128 + cbase] =
            make_float2(oac[nt][0]*inv1, oac[nt][1]*inv1);
        *(float2*)&out[n*HW_ + (r0+8)*128 + cbase] =
            make_float2(oac[nt][2]*inv2, oac[nt][3]*inv2);
    }
}

// ---------------------------------------------------------------------------
extern "C" void kernel_launch(void* const* d_in, const int* in_sizes, int n_in,
                              void* d_out, int out_size)
{
    const float* x  = (const float*)d_in[0];
    const float* e  = (const float*)d_in[1];
    const float* W1 = (const float*)d_in[2];
    const float* b1 = (const float*)d_in[3];
    const float* W2 = (const float*)d_in[4];
    const float* b2 = (const float*)d_in[5];
    const float* W3 = (const float*)d_in[6];
    const float* b3 = (const float*)d_in[7];
    float* out = (float*)d_out;

    const int smem1 = (64*128 + 16*128 + 64*68*2 + 16*68 + 3*64) * (int)sizeof(float);
    cudaFuncSetAttribute(qvk_kernel, cudaFuncAttributeMaxDynamicSharedMemorySize, smem1);
    qvk_kernel<<<dim3(128, 16), 256, smem1>>>(x, e, W1, b1, W2, b2, W3, b3);

    const int smem2 = (128*LDA + 128*LDB) * (int)sizeof(float);
    cudaFuncSetAttribute(attn_kernel, cudaFuncAttributeMaxDynamicSharedMemorySize, smem2);
    attn_kernel<<<NTOT, 256, smem2>>>(out);
}

// round 6
// speedup vs baseline: 1.1753x; 1.1753x over previous
#include <cuda_runtime.h>
#include <cstdint>

#define HW_ (128*128)
#define NTOT (16*64)

__device__ float g_Q[NTOT * HW_];
__device__ float g_V[NTOT * HW_];
__device__ float g_K[NTOT * HW_];

// ---------------------------------------------------------------------------
// Kernel 1: fused 1x1-conv projections (R1 scalar version — measured fastest).
// ---------------------------------------------------------------------------
__global__ __launch_bounds__(256) void qvk_kernel(
    const float* __restrict__ x, const float* __restrict__ e,
    const float* __restrict__ W1, const float* __restrict__ b1,
    const float* __restrict__ W2, const float* __restrict__ b2,
    const float* __restrict__ W3, const float* __restrict__ b3)
{
    extern __shared__ float sm[];
    float* Xs  = sm;               // [64][128]
    float* Es  = Xs + 64*128;      // [16][128]
    float* W2s = Es + 16*128;      // [64][68]
    float* W3s = W2s + 64*68;
    float* W1s = W3s + 64*68;      // [16][68]
    float* b1s = W1s + 16*68;
    float* b2s = b1s + 64;
    float* b3s = b2s + 64;

    const int tid = threadIdx.x;
    const int b   = blockIdx.y;
    const int p0  = blockIdx.x * 128;

    for (int idx = tid; idx < 4096; idx += 256) {
        int o = idx >> 6, c = idx & 63;
        W2s[c*68 + o] = W2[idx];
        W3s[c*68 + o] = W3[idx];
    }
    for (int idx = tid; idx < 1024; idx += 256) {
        int o = idx >> 4, c = idx & 15;
        W1s[c*68 + o] = W1[idx];
    }
    if (tid < 64) { b1s[tid] = b1[tid]; b2s[tid] = b2[tid]; b3s[tid] = b3[tid]; }

    for (int idx = tid; idx < 64*128; idx += 256) {
        int c = idx >> 7, p = idx & 127;
        Xs[idx] = x[(b*64 + c)*HW_ + p0 + p];
    }
    for (int idx = tid; idx < 16*128; idx += 256) {
        int c = idx >> 7, p = idx & 127;
        Es[idx] = e[(b*16 + c)*HW_ + p0 + p];
    }
    __syncthreads();

    const int oi = tid >> 4;
    const int pj = tid & 15;

    float accQ[4][8], accV[4][8], accK[4][8];
    #pragma unroll
    for (int i = 0; i < 4; i++) {
        float bq = b1s[oi*4+i], bv = b2s[oi*4+i], bk = b3s[oi*4+i];
        #pragma unroll
        for (int j = 0; j < 8; j++) { accQ[i][j] = bq; accV[i][j] = bv; accK[i][j] = bk; }
    }

    #pragma unroll 4
    for (int c = 0; c < 64; c++) {
        float4 a2v = *(const float4*)&W2s[c*68 + oi*4];
        float4 a3v = *(const float4*)&W3s[c*68 + oi*4];
        float4 x0  = *(const float4*)&Xs[c*128 + pj*8];
        float4 x1  = *(const float4*)&Xs[c*128 + pj*8 + 4];
        float av2[4] = {a2v.x, a2v.y, a2v.z, a2v.w};
        float av3[4] = {a3v.x, a3v.y, a3v.z, a3v.w};
        float xv[8]  = {x0.x, x0.y, x0.z, x0.w, x1.x, x1.y, x1.z, x1.w};
        #pragma unroll
        for (int i = 0; i < 4; i++)
            #pragma unroll
            for (int j = 0; j < 8; j++) {
                accV[i][j] += av2[i] * xv[j];
                accK[i][j] += av3[i] * xv[j];
            }
    }
    #pragma unroll 4
    for (int c = 0; c < 16; c++) {
        float4 a1v = *(const float4*)&W1s[c*68 + oi*4];
        float4 e0  = *(const float4*)&Es[c*128 + pj*8];
        float4 e1  = *(const float4*)&Es[c*128 + pj*8 + 4];
        float av1[4] = {a1v.x, a1v.y, a1v.z, a1v.w};
        float ev[8]  = {e0.x, e0.y, e0.z, e0.w, e1.x, e1.y, e1.z, e1.w};
        #pragma unroll
        for (int i = 0; i < 4; i++)
            #pragma unroll
            for (int j = 0; j < 8; j++)
                accQ[i][j] += av1[i] * ev[j];
    }

    #pragma unroll
    for (int i = 0; i < 4; i++) {
        int o  = oi*4 + i;
        int gb = (b*64 + o)*HW_ + p0 + pj*8;
        *(float4*)&g_Q[gb]     = make_float4(accQ[i][0], accQ[i][1], accQ[i][2], accQ[i][3]);
        *(float4*)&g_Q[gb + 4] = make_float4(accQ[i][4], accQ[i][5], accQ[i][6], accQ[i][7]);
        *(float4*)&g_V[gb]     = make_float4(accV[i][0], accV[i][1], accV[i][2], accV[i][3]);
        *(float4*)&g_V[gb + 4] = make_float4(accV[i][4], accV[i][5], accV[i][6], accV[i][7]);
        *(float4*)&g_K[gb]     = make_float4(accK[i][0], accK[i][1], accK[i][2], accK[i][3]);
        *(float4*)&g_K[gb + 4] = make_float4(accK[i][4], accK[i][5], accK[i][6], accK[i][7]);
    }
}

// ---------------------------------------------------------------------------
// Kernel 2: per-head attention on tensor cores, 512 threads (16 warps).
// Warp pair (wb, wb+8): wb -> output cols 0..63, wb+8 -> cols 64..127,
// both on row band wb*16..wb*16+15. Split-in-loop tf32 3-term (R4 scheme).
// ---------------------------------------------------------------------------
#define LDA 132

__device__ __forceinline__ void mma_tf32(float c[4], const uint32_t a[4],
                                         const uint32_t b0, const uint32_t b1) {
    asm volatile(
        "mma.sync.aligned.m16n8k8.row.col.f32.tf32.tf32.f32 "
        "{%0,%1,%2,%3}, {%4,%5,%6,%7}, {%8,%9}, {%0,%1,%2,%3};"
        : "+f"(c[0]), "+f"(c[1]), "+f"(c[2]), "+f"(c[3])
        : "r"(a[0]), "r"(a[1]), "r"(a[2]), "r"(a[3]), "r"(b0), "r"(b1));
}

__device__ __forceinline__ void tf32_split(float x, uint32_t& hi, uint32_t& lo) {
    hi = __float_as_uint(x) & 0xffffe000u;
    float r = x - __uint_as_float(hi);
    lo = __float_as_uint(r) & 0xffffe000u;
}

__global__ __launch_bounds__(512) void attn_kernel(float* __restrict__ out)
{
    extern __shared__ float sm[];
    float* A    = sm;              // Q[h][w] -> later P[h][g]
    float* Bm   = sm + 128*LDA;    // V[g][w] -> later K[g][w]
    float* redM = sm + 2*128*LDA;  // [2][128] partial max
    float* redS = redM + 2*128;    // [2][128] partial sum

    const int tid  = threadIdx.x;
    const int warp = tid >> 5;
    const int lane = tid & 31;
    const int wb   = warp & 7;     // row band
    const int wh   = warp >> 3;    // column half (0: cols 0..63, 1: 64..127)
    const int n    = blockIdx.x;
    const float* Q = g_Q + n*HW_;
    const float* V = g_V + n*HW_;
    const float* K = g_K + n*HW_;

    for (int idx = tid; idx < 128*32; idx += 512) {
        int row = idx >> 5, c4 = (idx & 31) * 4;
        *(float4*)&A[row*LDA + c4]  = *(const float4*)&Q[row*128 + c4];
        *(float4*)&Bm[row*LDA + c4] = *(const float4*)&V[row*128 + c4];
    }
    __syncthreads();

    const int g4 = lane >> 2;        // 0..7
    const int tg = lane & 3;         // 0..3
    const int r0 = wb*16 + g4;       // rows r0 (c0/c1) and r0+8 (c2/c3)
    const int nt0 = wh*8;            // first n-tile of this warp's half

    float acc[8][4];
    #pragma unroll
    for (int j = 0; j < 8; j++)
        #pragma unroll
        for (int i = 0; i < 4; i++) acc[j][i] = 0.0f;

    // ---- Phase A: S = Q @ V^T (this warp's 8 n-tiles)
    #pragma unroll 1
    for (int k = 0; k < 16; k++) {
        const int kb = k*8 + tg;
        uint32_t ah[4], al[4];
        tf32_split(A[r0*LDA + kb],         ah[0], al[0]);
        tf32_split(A[(r0+8)*LDA + kb],     ah[1], al[1]);
        tf32_split(A[r0*LDA + kb + 4],     ah[2], al[2]);
        tf32_split(A[(r0+8)*LDA + kb + 4], ah[3], al[3]);
        #pragma unroll
        for (int j = 0; j < 8; j++) {
            const int gc = (nt0 + j)*8 + g4;
            uint32_t bh0, bl0, bh1, bl1;
            tf32_split(Bm[gc*LDA + kb],     bh0, bl0);
            tf32_split(Bm[gc*LDA + kb + 4], bh1, bl1);
            mma_tf32(acc[j], ah, bh0, bh1);
            mma_tf32(acc[j], al, bh0, bh1);
            mma_tf32(acc[j], ah, bl0, bl1);
        }
    }

    // ---- Softmax: partial max over this half, combine across warp pair
    float m1 = -1e30f, m2 = -1e30f;
    #pragma unroll
    for (int j = 0; j < 8; j++) {
        m1 = fmaxf(m1, fmaxf(acc[j][0], acc[j][1]));
        m2 = fmaxf(m2, fmaxf(acc[j][2], acc[j][3]));
    }
    #pragma unroll
    for (int off = 1; off < 4; off <<= 1) {
        m1 = fmaxf(m1, __shfl_xor_sync(0xFFFFFFFFu, m1, off));
        m2 = fmaxf(m2, __shfl_xor_sync(0xFFFFFFFFu, m2, off));
    }
    if (tg == 0) {
        redM[wh*128 + r0]     = m1;
        redM[wh*128 + r0 + 8] = m2;
    }
    __syncthreads();   // phase-A reads of A/Bm done + partial maxes visible

    const float gm1 = fmaxf(redM[r0],     redM[128 + r0]);
    const float gm2 = fmaxf(redM[r0 + 8], redM[128 + r0 + 8]);

    float s1 = 0.0f, s2 = 0.0f;
    #pragma unroll
    for (int j = 0; j < 8; j++) {
        acc[j][0] = __expf(acc[j][0] - gm1);
        acc[j][1] = __expf(acc[j][1] - gm1);
        acc[j][2] = __expf(acc[j][2] - gm2);
        acc[j][3] = __expf(acc[j][3] - gm2);
        s1 += acc[j][0] + acc[j][1];
        s2 += acc[j][2] + acc[j][3];
    }
    #pragma unroll
    for (int off = 1; off < 4; off <<= 1) {
        s1 += __shfl_xor_sync(0xFFFFFFFFu, s1, off);
        s2 += __shfl_xor_sync(0xFFFFFFFFu, s2, off);
    }
    if (tg == 0) {
        redS[wh*128 + r0]     = s1;
        redS[wh*128 + r0 + 8] = s2;
    }

    // Store unnormalized P into A (disjoint column halves per warp)
    #pragma unroll
    for (int j = 0; j < 8; j++) {
        const int cb = (nt0 + j)*8 + 2*tg;
        *(float2*)&A[r0*LDA     + cb] = make_float2(acc[j][0], acc[j][1]);
        *(float2*)&A[(r0+8)*LDA + cb] = make_float2(acc[j][2], acc[j][3]);
    }
    // Stage K into Bm (V no longer needed)
    for (int idx = tid; idx < 128*32; idx += 512) {
        int row = idx >> 5, c4 = (idx & 31) * 4;
        *(float4*)&Bm[row*LDA + c4] = *(const float4*)&K[row*128 + c4];
    }
    __syncthreads();   // P complete, K staged, partial sums visible

    const float inv1 = 1.0f / (redS[r0]     + redS[128 + r0]);
    const float inv2 = 1.0f / (redS[r0 + 8] + redS[128 + r0 + 8]);

    // ---- Phase C: ctx = P @ K (this warp's 8 n-tiles, full k)
    float oac[8][4];
    #pragma unroll
    for (int j = 0; j < 8; j++)
        #pragma unroll
        for (int i = 0; i < 4; i++) oac[j][i] = 0.0f;

    #pragma unroll 1
    for (int k = 0; k < 16; k++) {
        const int kb = k*8 + tg;
        uint32_t ah[4], al[4];
        tf32_split(A[r0*LDA + kb],         ah[0], al[0]);
        tf32_split(A[(r0+8)*LDA + kb],     ah[1], al[1]);
        tf32_split(A[r0*LDA + kb + 4],     ah[2], al[2]);
        tf32_split(A[(r0+8)*LDA + kb + 4], ah[3], al[3]);
        #pragma unroll
        for (int j = 0; j < 8; j++) {
            const int nc = (nt0 + j)*8 + g4;
            uint32_t bh0, bl0, bh1, bl1;
            tf32_split(Bm[kb*LDA + nc],     bh0, bl0);
            tf32_split(Bm[(kb+4)*LDA + nc], bh1, bl1);
            mma_tf32(oac[j], ah, bh0, bh1);
            mma_tf32(oac[j], al, bh0, bh1);
            mma_tf32(oac[j], ah, bl0, bl1);
        }
    }

    // Epilogue
    #pragma unroll
    for (int j = 0; j < 8; j++) {
        const int cb = (nt0 + j)*8 + 2*tg;
        *(float2*)&out[n*HW_ + r0*128 + cb] =
            make_float2(oac[j][0]*inv1, oac[j][1]*inv1);
        *(float2*)&out[n*HW_ + (r0+8)*128 + cb] =
            make_float2(oac[j][2]*inv2, oac[j][3]*inv2);
    }
}

// ---------------------------------------------------------------------------
extern "C" void kernel_launch(void* const* d_in, const int* in_sizes, int n_in,
                              void* d_out, int out_size)
{
    const float* x  = (const float*)d_in[0];
    const float* e  = (const float*)d_in[1];
    const float* W1 = (const float*)d_in[2];
    const float* b1 = (const float*)d_in[3];
    const float* W2 = (const float*)d_in[4];
    const float* b2 = (const float*)d_in[5];
    const float* W3 = (const float*)d_in[6];
    const float* b3 = (const float*)d_in[7];
    float* out = (float*)d_out;

    const int smem1 = (64*128 + 16*128 + 64*68*2 + 16*68 + 3*64) * (int)sizeof(float);
    cudaFuncSetAttribute(qvk_kernel, cudaFuncAttributeMaxDynamicSharedMemorySize, smem1);
    qvk_kernel<<<dim3(128, 16), 256, smem1>>>(x, e, W1, b1, W2, b2, W3, b3);

    const int smem2 = (2*128*LDA + 4*128) * (int)sizeof(float);
    cudaFuncSetAttribute(attn_kernel, cudaFuncAttributeMaxDynamicSharedMemorySize, smem2);
    attn_kernel<<<NTOT, 512, smem2>>>(out);
}

// round 7
// speedup vs baseline: 1.3456x; 1.1449x over previous
#include <cuda_runtime.h>
#include <cstdint>

#define HW_ (128*128)
#define NTOT (16*64)

__device__ float g_Q[NTOT * HW_];
__device__ float g_V[NTOT * HW_];
__device__ float g_K[NTOT * HW_];

__device__ __forceinline__ void mma_tf32(float c[4], const uint32_t a[4],
                                         const uint32_t b0, const uint32_t b1) {
    asm volatile(
        "mma.sync.aligned.m16n8k8.row.col.f32.tf32.tf32.f32 "
        "{%0,%1,%2,%3}, {%4,%5,%6,%7}, {%8,%9}, {%0,%1,%2,%3};"
        : "+f"(c[0]), "+f"(c[1]), "+f"(c[2]), "+f"(c[3])
        : "r"(a[0]), "r"(a[1]), "r"(a[2]), "r"(a[3]), "r"(b0), "r"(b1));
}

__device__ __forceinline__ void tf32_split(float x, uint32_t& hi, uint32_t& lo) {
    hi = __float_as_uint(x) & 0xffffe000u;
    float r = x - __uint_as_float(hi);
    lo = __float_as_uint(r) & 0xffffe000u;
}

// ---------------------------------------------------------------------------
// Kernel 1: fused 1x1-conv projections on tensor cores (tf32 3-split).
// 512 thr / 16 warps. Warp (wb, wh): pixel tile p0 = bx*128 + wb*16,
// output-channel half o0 = wh*32. V/K share X b-fragments; W pre-split in smem.
// ---------------------------------------------------------------------------
__global__ __launch_bounds__(512) void qvk_kernel(
    const float* __restrict__ x, const float* __restrict__ e,
    const float* __restrict__ W1, const float* __restrict__ b1,
    const float* __restrict__ W2, const float* __restrict__ b2,
    const float* __restrict__ W3, const float* __restrict__ b3)
{
    extern __shared__ float sm[];
    float* W2h = sm;                 // [64][68]
    float* W2l = W2h + 64*68;
    float* W3h = W2l + 64*68;
    float* W3l = W3h + 64*68;
    float* W1h = W3l + 64*68;        // [64][20]
    float* W1l = W1h + 64*20;
    float* b1s = W1l + 64*20;
    float* b2s = b1s + 64;
    float* b3s = b2s + 64;

    const int tid = threadIdx.x;

    for (int idx = tid; idx < 4096; idx += 512) {
        int o = idx >> 6, c = idx & 63;
        uint32_t hi, lo;
        tf32_split(W2[idx], hi, lo);
        W2h[o*68 + c] = __uint_as_float(hi);
        W2l[o*68 + c] = __uint_as_float(lo);
        tf32_split(W3[idx], hi, lo);
        W3h[o*68 + c] = __uint_as_float(hi);
        W3l[o*68 + c] = __uint_as_float(lo);
    }
    for (int idx = tid; idx < 1024; idx += 512) {
        int o = idx >> 4, c = idx & 15;
        uint32_t hi, lo;
        tf32_split(W1[idx], hi, lo);
        W1h[o*20 + c] = __uint_as_float(hi);
        W1l[o*20 + c] = __uint_as_float(lo);
    }
    if (tid < 64) { b1s[tid] = b1[tid]; b2s[tid] = b2[tid]; b3s[tid] = b3[tid]; }
    __syncthreads();

    const int warp = tid >> 5;
    const int lane = tid & 31;
    const int g4 = lane >> 2;
    const int tg = lane & 3;
    const int wb = warp & 7;      // pixel sub-tile
    const int wh = warp >> 3;     // output-channel half
    const int b  = blockIdx.y;
    const int p0 = blockIdx.x*128 + wb*16;
    const int o0 = wh*32;

    const float* xb = x + b*64*HW_;
    const float* eb = e + b*16*HW_;

    float accV[2][2][4], accK[2][2][4], accQ[2][2][4];
    #pragma unroll
    for (int mt = 0; mt < 2; mt++) {
        int r = o0 + mt*16 + g4;
        float v0 = b2s[r], v1 = b2s[r+8];
        float k0 = b3s[r], k1 = b3s[r+8];
        float q0 = b1s[r], q1 = b1s[r+8];
        #pragma unroll
        for (int ntl = 0; ntl < 2; ntl++) {
            accV[mt][ntl][0] = v0; accV[mt][ntl][1] = v0;
            accV[mt][ntl][2] = v1; accV[mt][ntl][3] = v1;
            accK[mt][ntl][0] = k0; accK[mt][ntl][1] = k0;
            accK[mt][ntl][2] = k1; accK[mt][ntl][3] = k1;
            accQ[mt][ntl][0] = q0; accQ[mt][ntl][1] = q0;
            accQ[mt][ntl][2] = q1; accQ[mt][ntl][3] = q1;
        }
    }

    // ---- V, K over C=64 (X b-fragments straight from gmem, shared by V & K)
    #pragma unroll 2
    for (int ks = 0; ks < 8; ks++) {
        const int c0 = ks*8;
        uint32_t bh[2][2], bl[2][2];
        #pragma unroll
        for (int ntl = 0; ntl < 2; ntl++) {
            int pcol = p0 + ntl*8 + g4;
            tf32_split(xb[(c0+tg)*HW_ + pcol],   bh[ntl][0], bl[ntl][0]);
            tf32_split(xb[(c0+tg+4)*HW_ + pcol], bh[ntl][1], bl[ntl][1]);
        }
        #pragma unroll
        for (int mt = 0; mt < 2; mt++) {
            const int rb = (o0 + mt*16 + g4)*68 + c0 + tg;
            uint32_t ah[4], al[4];
            ah[0] = __float_as_uint(W2h[rb]);
            ah[1] = __float_as_uint(W2h[rb + 8*68]);
            ah[2] = __float_as_uint(W2h[rb + 4]);
            ah[3] = __float_as_uint(W2h[rb + 8*68 + 4]);
            al[0] = __float_as_uint(W2l[rb]);
            al[1] = __float_as_uint(W2l[rb + 8*68]);
            al[2] = __float_as_uint(W2l[rb + 4]);
            al[3] = __float_as_uint(W2l[rb + 8*68 + 4]);
            #pragma unroll
            for (int ntl = 0; ntl < 2; ntl++) {
                mma_tf32(accV[mt][ntl], ah, bh[ntl][0], bh[ntl][1]);
                mma_tf32(accV[mt][ntl], al, bh[ntl][0], bh[ntl][1]);
                mma_tf32(accV[mt][ntl], ah, bl[ntl][0], bl[ntl][1]);
            }
            ah[0] = __float_as_uint(W3h[rb]);
            ah[1] = __float_as_uint(W3h[rb + 8*68]);
            ah[2] = __float_as_uint(W3h[rb + 4]);
            ah[3] = __float_as_uint(W3h[rb + 8*68 + 4]);
            al[0] = __float_as_uint(W3l[rb]);
            al[1] = __float_as_uint(W3l[rb + 8*68]);
            al[2] = __float_as_uint(W3l[rb + 4]);
            al[3] = __float_as_uint(W3l[rb + 8*68 + 4]);
            #pragma unroll
            for (int ntl = 0; ntl < 2; ntl++) {
                mma_tf32(accK[mt][ntl], ah, bh[ntl][0], bh[ntl][1]);
                mma_tf32(accK[mt][ntl], al, bh[ntl][0], bh[ntl][1]);
                mma_tf32(accK[mt][ntl], ah, bl[ntl][0], bl[ntl][1]);
            }
        }
    }

    // ---- Q over C1=16 (from e, W1)
    #pragma unroll
    for (int ks = 0; ks < 2; ks++) {
        const int c0 = ks*8;
        uint32_t bh[2][2], bl[2][2];
        #pragma unroll
        for (int ntl = 0; ntl < 2; ntl++) {
            int pcol = p0 + ntl*8 + g4;
            tf32_split(eb[(c0+tg)*HW_ + pcol],   bh[ntl][0], bl[ntl][0]);
            tf32_split(eb[(c0+tg+4)*HW_ + pcol], bh[ntl][1], bl[ntl][1]);
        }
        #pragma unroll
        for (int mt = 0; mt < 2; mt++) {
            const int rb = (o0 + mt*16 + g4)*20 + c0 + tg;
            uint32_t ah[4], al[4];
            ah[0] = __float_as_uint(W1h[rb]);
            ah[1] = __float_as_uint(W1h[rb + 8*20]);
            ah[2] = __float_as_uint(W1h[rb + 4]);
            ah[3] = __float_as_uint(W1h[rb + 8*20 + 4]);
            al[0] = __float_as_uint(W1l[rb]);
            al[1] = __float_as_uint(W1l[rb + 8*20]);
            al[2] = __float_as_uint(W1l[rb + 4]);
            al[3] = __float_as_uint(W1l[rb + 8*20 + 4]);
            #pragma unroll
            for (int ntl = 0; ntl < 2; ntl++) {
                mma_tf32(accQ[mt][ntl], ah, bh[ntl][0], bh[ntl][1]);
                mma_tf32(accQ[mt][ntl], al, bh[ntl][0], bh[ntl][1]);
                mma_tf32(accQ[mt][ntl], ah, bl[ntl][0], bl[ntl][1]);
            }
        }
    }

    // ---- Store (float2 per row-pair, coalesced in 32B sectors)
    #pragma unroll
    for (int mt = 0; mt < 2; mt++) {
        int r = o0 + mt*16 + g4;
        #pragma unroll
        for (int ntl = 0; ntl < 2; ntl++) {
            int pc = p0 + ntl*8 + 2*tg;
            int i0 = (b*64 + r)*HW_ + pc;
            int i1 = (b*64 + r + 8)*HW_ + pc;
            *(float2*)&g_V[i0] = make_float2(accV[mt][ntl][0], accV[mt][ntl][1]);
            *(float2*)&g_V[i1] = make_float2(accV[mt][ntl][2], accV[mt][ntl][3]);
            *(float2*)&g_K[i0] = make_float2(accK[mt][ntl][0], accK[mt][ntl][1]);
            *(float2*)&g_K[i1] = make_float2(accK[mt][ntl][2], accK[mt][ntl][3]);
            *(float2*)&g_Q[i0] = make_float2(accQ[mt][ntl][0], accQ[mt][ntl][1]);
            *(float2*)&g_Q[i1] = make_float2(accQ[mt][ntl][2], accQ[mt][ntl][3]);
        }
    }
}

// ---------------------------------------------------------------------------
// Kernel 2: per-head attention on tensor cores, 512 threads (R6 winner).
// ---------------------------------------------------------------------------
#define LDA 132

__global__ __launch_bounds__(512) void attn_kernel(float* __restrict__ out)
{
    extern __shared__ float sm[];
    float* A    = sm;              // Q[h][w] -> later P[h][g]
    float* Bm   = sm + 128*LDA;    // V[g][w] -> later K[g][w]
    float* redM = sm + 2*128*LDA;  // [2][128] partial max
    float* redS = redM + 2*128;    // [2][128] partial sum

    const int tid  = threadIdx.x;
    const int warp = tid >> 5;
    const int lane = tid & 31;
    const int wb   = warp & 7;     // row band
    const int wh   = warp >> 3;    // column half
    const int n    = blockIdx.x;
    const float* Q = g_Q + n*HW_;
    const float* V = g_V + n*HW_;
    const float* K = g_K + n*HW_;

    for (int idx = tid; idx < 128*32; idx += 512) {
        int row = idx >> 5, c4 = (idx & 31) * 4;
        *(float4*)&A[row*LDA + c4]  = *(const float4*)&Q[row*128 + c4];
        *(float4*)&Bm[row*LDA + c4] = *(const float4*)&V[row*128 + c4];
    }
    __syncthreads();

    const int g4 = lane >> 2;
    const int tg = lane & 3;
    const int r0 = wb*16 + g4;
    const int nt0 = wh*8;

    float acc[8][4];
    #pragma unroll
    for (int j = 0; j < 8; j++)
        #pragma unroll
        for (int i = 0; i < 4; i++) acc[j][i] = 0.0f;

    #pragma unroll 1
    for (int k = 0; k < 16; k++) {
        const int kb = k*8 + tg;
        uint32_t ah[4], al[4];
        tf32_split(A[r0*LDA + kb],         ah[0], al[0]);
        tf32_split(A[(r0+8)*LDA + kb],     ah[1], al[1]);
        tf32_split(A[r0*LDA + kb + 4],     ah[2], al[2]);
        tf32_split(A[(r0+8)*LDA + kb + 4], ah[3], al[3]);
        #pragma unroll
        for (int j = 0; j < 8; j++) {
            const int gc = (nt0 + j)*8 + g4;
            uint32_t bh0, bl0, bh1, bl1;
            tf32_split(Bm[gc*LDA + kb],     bh0, bl0);
            tf32_split(Bm[gc*LDA + kb + 4], bh1, bl1);
            mma_tf32(acc[j], ah, bh0, bh1);
            mma_tf32(acc[j], al, bh0, bh1);
            mma_tf32(acc[j], ah, bl0, bl1);
        }
    }

    float m1 = -1e30f, m2 = -1e30f;
    #pragma unroll
    for (int j = 0; j < 8; j++) {
        m1 = fmaxf(m1, fmaxf(acc[j][0], acc[j][1]));
        m2 = fmaxf(m2, fmaxf(acc[j][2], acc[j][3]));
    }
    #pragma unroll
    for (int off = 1; off < 4; off <<= 1) {
        m1 = fmaxf(m1, __shfl_xor_sync(0xFFFFFFFFu, m1, off));
        m2 = fmaxf(m2, __shfl_xor_sync(0xFFFFFFFFu, m2, off));
    }
    if (tg == 0) {
        redM[wh*128 + r0]     = m1;
        redM[wh*128 + r0 + 8] = m2;
    }
    __syncthreads();

    const float gm1 = fmaxf(redM[r0],     redM[128 + r0]);
    const float gm2 = fmaxf(redM[r0 + 8], redM[128 + r0 + 8]);

    float s1 = 0.0f, s2 = 0.0f;
    #pragma unroll
    for (int j = 0; j < 8; j++) {
        acc[j][0] = __expf(acc[j][0] - gm1);
        acc[j][1] = __expf(acc[j][1] - gm1);
        acc[j][2] = __expf(acc[j][2] - gm2);
        acc[j][3] = __expf(acc[j][3] - gm2);
        s1 += acc[j][0] + acc[j][1];
        s2 += acc[j][2] + acc[j][3];
    }
    #pragma unroll
    for (int off = 1; off < 4; off <<= 1) {
        s1 += __shfl_xor_sync(0xFFFFFFFFu, s1, off);
        s2 += __shfl_xor_sync(0xFFFFFFFFu, s2, off);
    }
    if (tg == 0) {
        redS[wh*128 + r0]     = s1;
        redS[wh*128 + r0 + 8] = s2;
    }

    #pragma unroll
    for (int j = 0; j < 8; j++) {
        const int cb = (nt0 + j)*8 + 2*tg;
        *(float2*)&A[r0*LDA     + cb] = make_float2(acc[j][0], acc[j][1]);
        *(float2*)&A[(r0+8)*LDA + cb] = make_float2(acc[j][2], acc[j][3]);
    }
    for (int idx = tid; idx < 128*32; idx += 512) {
        int row = idx >> 5, c4 = (idx & 31) * 4;
        *(float4*)&Bm[row*LDA + c4] = *(const float4*)&K[row*128 + c4];
    }
    __syncthreads();

    const float inv1 = 1.0f / (redS[r0]     + redS[128 + r0]);
    const float inv2 = 1.0f / (redS[r0 + 8] + redS[128 + r0 + 8]);

    float oac[8][4];
    #pragma unroll
    for (int j = 0; j < 8; j++)
        #pragma unroll
        for (int i = 0; i < 4; i++) oac[j][i] = 0.0f;

    #pragma unroll 1
    for (int k = 0; k < 16; k++) {
        const int kb = k*8 + tg;
        uint32_t ah[4], al[4];
        tf32_split(A[r0*LDA + kb],         ah[0], al[0]);
        tf32_split(A[(r0+8)*LDA + kb],     ah[1], al[1]);
        tf32_split(A[r0*LDA + kb + 4],     ah[2], al[2]);
        tf32_split(A[(r0+8)*LDA + kb + 4], ah[3], al[3]);
        #pragma unroll
        for (int j = 0; j < 8; j++) {
            const int nc = (nt0 + j)*8 + g4;
            uint32_t bh0, bl0, bh1, bl1;
            tf32_split(Bm[kb*LDA + nc],     bh0, bl0);
            tf32_split(Bm[(kb+4)*LDA + nc], bh1, bl1);
            mma_tf32(oac[j], ah, bh0, bh1);
            mma_tf32(oac[j], al, bh0, bh1);
            mma_tf32(oac[j], ah, bl0, bl1);
        }
    }

    #pragma unroll
    for (int j = 0; j < 8; j++) {
        const int cb = (nt0 + j)*8 + 2*tg;
        *(float2*)&out[n*HW_ + r0*128 + cb] =
            make_float2(oac[j][0]*inv1, oac[j][1]*inv1);
        *(float2*)&out[n*HW_ + (r0+8)*128 + cb] =
            make_float2(oac[j][2]*inv2, oac[j][3]*inv2);
    }
}

// ---------------------------------------------------------------------------
extern "C" void kernel_launch(void* const* d_in, const int* in_sizes, int n_in,
                              void* d_out, int out_size)
{
    const float* x  = (const float*)d_in[0];
    const float* e  = (const float*)d_in[1];
    const float* W1 = (const float*)d_in[2];
    const float* b1 = (const float*)d_in[3];
    const float* W2 = (const float*)d_in[4];
    const float* b2 = (const float*)d_in[5];
    const float* W3 = (const float*)d_in[6];
    const float* b3 = (const float*)d_in[7];
    float* out = (float*)d_out;

    const int smem1 = (4*64*68 + 2*64*20 + 3*64) * (int)sizeof(float);
    cudaFuncSetAttribute(qvk_kernel, cudaFuncAttributeMaxDynamicSharedMemorySize, smem1);
    qvk_kernel<<<dim3(128, 16), 512, smem1>>>(x, e, W1, b1, W2, b2, W3, b3);

    const int smem2 = (2*128*LDA + 4*128) * (int)sizeof(float);
    cudaFuncSetAttribute(attn_kernel, cudaFuncAttributeMaxDynamicSharedMemorySize, smem2);
    attn_kernel<<<NTOT, 512, smem2>>>(out);
}

// round 8
// speedup vs baseline: 1.4194x; 1.0548x over previous
#include <cuda_runtime.h>
#include <cstdint>

#define HW_ (128*128)
#define NTOT (16*64)

__device__ float g_Q[NTOT * HW_];
__device__ float g_V[NTOT * HW_];
__device__ float g_K[NTOT * HW_];

__device__ __forceinline__ void mma_tf32(float c[4], const uint32_t a[4],
                                         const uint32_t b0, const uint32_t b1) {
    asm volatile(
        "mma.sync.aligned.m16n8k8.row.col.f32.tf32.tf32.f32 "
        "{%0,%1,%2,%3}, {%4,%5,%6,%7}, {%8,%9}, {%0,%1,%2,%3};"
        : "+f"(c[0]), "+f"(c[1]), "+f"(c[2]), "+f"(c[3])
        : "r"(a[0]), "r"(a[1]), "r"(a[2]), "r"(a[3]), "r"(b0), "r"(b1));
}

__device__ __forceinline__ void tf32_split(float x, uint32_t& hi, uint32_t& lo) {
    hi = __float_as_uint(x) & 0xffffe000u;
    float r = x - __uint_as_float(hi);
    lo = __float_as_uint(r) & 0xffffe000u;
}

// ---------------------------------------------------------------------------
// Kernel 1: fused 1x1-conv projections on tensor cores (unchanged R7 winner).
// ---------------------------------------------------------------------------
__global__ __launch_bounds__(512) void qvk_kernel(
    const float* __restrict__ x, const float* __restrict__ e,
    const float* __restrict__ W1, const float* __restrict__ b1,
    const float* __restrict__ W2, const float* __restrict__ b2,
    const float* __restrict__ W3, const float* __restrict__ b3)
{
    extern __shared__ float sm[];
    float* W2h = sm;                 // [64][68]
    float* W2l = W2h + 64*68;
    float* W3h = W2l + 64*68;
    float* W3l = W3h + 64*68;
    float* W1h = W3l + 64*68;        // [64][20]
    float* W1l = W1h + 64*20;
    float* b1s = W1l + 64*20;
    float* b2s = b1s + 64;
    float* b3s = b2s + 64;

    const int tid = threadIdx.x;

    for (int idx = tid; idx < 4096; idx += 512) {
        int o = idx >> 6, c = idx & 63;
        uint32_t hi, lo;
        tf32_split(W2[idx], hi, lo);
        W2h[o*68 + c] = __uint_as_float(hi);
        W2l[o*68 + c] = __uint_as_float(lo);
        tf32_split(W3[idx], hi, lo);
        W3h[o*68 + c] = __uint_as_float(hi);
        W3l[o*68 + c] = __uint_as_float(lo);
    }
    for (int idx = tid; idx < 1024; idx += 512) {
        int o = idx >> 4, c = idx & 15;
        uint32_t hi, lo;
        tf32_split(W1[idx], hi, lo);
        W1h[o*20 + c] = __uint_as_float(hi);
        W1l[o*20 + c] = __uint_as_float(lo);
    }
    if (tid < 64) { b1s[tid] = b1[tid]; b2s[tid] = b2[tid]; b3s[tid] = b3[tid]; }
    __syncthreads();

    const int warp = tid >> 5;
    const int lane = tid & 31;
    const int g4 = lane >> 2;
    const int tg = lane & 3;
    const int wb = warp & 7;
    const int wh = warp >> 3;
    const int b  = blockIdx.y;
    const int p0 = blockIdx.x*128 + wb*16;
    const int o0 = wh*32;

    const float* xb = x + b*64*HW_;
    const float* eb = e + b*16*HW_;

    float accV[2][2][4], accK[2][2][4], accQ[2][2][4];
    #pragma unroll
    for (int mt = 0; mt < 2; mt++) {
        int r = o0 + mt*16 + g4;
        float v0 = b2s[r], v1 = b2s[r+8];
        float k0 = b3s[r], k1 = b3s[r+8];
        float q0 = b1s[r], q1 = b1s[r+8];
        #pragma unroll
        for (int ntl = 0; ntl < 2; ntl++) {
            accV[mt][ntl][0] = v0; accV[mt][ntl][1] = v0;
            accV[mt][ntl][2] = v1; accV[mt][ntl][3] = v1;
            accK[mt][ntl][0] = k0; accK[mt][ntl][1] = k0;
            accK[mt][ntl][2] = k1; accK[mt][ntl][3] = k1;
            accQ[mt][ntl][0] = q0; accQ[mt][ntl][1] = q0;
            accQ[mt][ntl][2] = q1; accQ[mt][ntl][3] = q1;
        }
    }

    #pragma unroll 2
    for (int ks = 0; ks < 8; ks++) {
        const int c0 = ks*8;
        uint32_t bh[2][2], bl[2][2];
        #pragma unroll
        for (int ntl = 0; ntl < 2; ntl++) {
            int pcol = p0 + ntl*8 + g4;
            tf32_split(xb[(c0+tg)*HW_ + pcol],   bh[ntl][0], bl[ntl][0]);
            tf32_split(xb[(c0+tg+4)*HW_ + pcol], bh[ntl][1], bl[ntl][1]);
        }
        #pragma unroll
        for (int mt = 0; mt < 2; mt++) {
            const int rb = (o0 + mt*16 + g4)*68 + c0 + tg;
            uint32_t ah[4], al[4];
            ah[0] = __float_as_uint(W2h[rb]);
            ah[1] = __float_as_uint(W2h[rb + 8*68]);
            ah[2] = __float_as_uint(W2h[rb + 4]);
            ah[3] = __float_as_uint(W2h[rb + 8*68 + 4]);
            al[0] = __float_as_uint(W2l[rb]);
            al[1] = __float_as_uint(W2l[rb + 8*68]);
            al[2] = __float_as_uint(W2l[rb + 4]);
            al[3] = __float_as_uint(W2l[rb + 8*68 + 4]);
            #pragma unroll
            for (int ntl = 0; ntl < 2; ntl++) {
                mma_tf32(accV[mt][ntl], ah, bh[ntl][0], bh[ntl][1]);
                mma_tf32(accV[mt][ntl], al, bh[ntl][0], bh[ntl][1]);
                mma_tf32(accV[mt][ntl], ah, bl[ntl][0], bl[ntl][1]);
            }
            ah[0] = __float_as_uint(W3h[rb]);
            ah[1] = __float_as_uint(W3h[rb + 8*68]);
            ah[2] = __float_as_uint(W3h[rb + 4]);
            ah[3] = __float_as_uint(W3h[rb + 8*68 + 4]);
            al[0] = __float_as_uint(W3l[rb]);
            al[1] = __float_as_uint(W3l[rb + 8*68]);
            al[2] = __float_as_uint(W3l[rb + 4]);
            al[3] = __float_as_uint(W3l[rb + 8*68 + 4]);
            #pragma unroll
            for (int ntl = 0; ntl < 2; ntl++) {
                mma_tf32(accK[mt][ntl], ah, bh[ntl][0], bh[ntl][1]);
                mma_tf32(accK[mt][ntl], al, bh[ntl][0], bh[ntl][1]);
                mma_tf32(accK[mt][ntl], ah, bl[ntl][0], bl[ntl][1]);
            }
        }
    }

    #pragma unroll
    for (int ks = 0; ks < 2; ks++) {
        const int c0 = ks*8;
        uint32_t bh[2][2], bl[2][2];
        #pragma unroll
        for (int ntl = 0; ntl < 2; ntl++) {
            int pcol = p0 + ntl*8 + g4;
            tf32_split(eb[(c0+tg)*HW_ + pcol],   bh[ntl][0], bl[ntl][0]);
            tf32_split(eb[(c0+tg+4)*HW_ + pcol], bh[ntl][1], bl[ntl][1]);
        }
        #pragma unroll
        for (int mt = 0; mt < 2; mt++) {
            const int rb = (o0 + mt*16 + g4)*20 + c0 + tg;
            uint32_t ah[4], al[4];
            ah[0] = __float_as_uint(W1h[rb]);
            ah[1] = __float_as_uint(W1h[rb + 8*20]);
            ah[2] = __float_as_uint(W1h[rb + 4]);
            ah[3] = __float_as_uint(W1h[rb + 8*20 + 4]);
            al[0] = __float_as_uint(W1l[rb]);
            al[1] = __float_as_uint(W1l[rb + 8*20]);
            al[2] = __float_as_uint(W1l[rb + 4]);
            al[3] = __float_as_uint(W1l[rb + 8*20 + 4]);
            #pragma unroll
            for (int ntl = 0; ntl < 2; ntl++) {
                mma_tf32(accQ[mt][ntl], ah, bh[ntl][0], bh[ntl][1]);
                mma_tf32(accQ[mt][ntl], al, bh[ntl][0], bh[ntl][1]);
                mma_tf32(accQ[mt][ntl], ah, bl[ntl][0], bl[ntl][1]);
            }
        }
    }

    #pragma unroll
    for (int mt = 0; mt < 2; mt++) {
        int r = o0 + mt*16 + g4;
        #pragma unroll
        for (int ntl = 0; ntl < 2; ntl++) {
            int pc = p0 + ntl*8 + 2*tg;
            int i0 = (b*64 + r)*HW_ + pc;
            int i1 = (b*64 + r + 8)*HW_ + pc;
            *(float2*)&g_V[i0] = make_float2(accV[mt][ntl][0], accV[mt][ntl][1]);
            *(float2*)&g_V[i1] = make_float2(accV[mt][ntl][2], accV[mt][ntl][3]);
            *(float2*)&g_K[i0] = make_float2(accK[mt][ntl][0], accK[mt][ntl][1]);
            *(float2*)&g_K[i1] = make_float2(accK[mt][ntl][2], accK[mt][ntl][3]);
            *(float2*)&g_Q[i0] = make_float2(accQ[mt][ntl][0], accQ[mt][ntl][1]);
            *(float2*)&g_Q[i1] = make_float2(accQ[mt][ntl][2], accQ[mt][ntl][3]);
        }
    }
}

// ---------------------------------------------------------------------------
// Kernel 2: per-head attention on tensor cores, 1024 threads (32 warps).
// Warp (wb, wq): row band wb*16, column quarter wq*32 (4 n-tiles).
// ---------------------------------------------------------------------------
#define LDA 132

__global__ __launch_bounds__(1024) void attn_kernel(float* __restrict__ out)
{
    extern __shared__ float sm[];
    float* A    = sm;              // Q[h][w] -> later P[h][g]
    float* Bm   = sm + 128*LDA;    // V[g][w] -> later K[g][w]
    float* redM = sm + 2*128*LDA;  // [4][128] partial max
    float* redS = redM + 4*128;    // [4][128] partial sum

    const int tid  = threadIdx.x;
    const int warp = tid >> 5;
    const int lane = tid & 31;
    const int wb   = warp & 7;     // row band
    const int wq   = warp >> 3;    // column quarter (0..3)
    const int n    = blockIdx.x;
    const float* Q = g_Q + n*HW_;
    const float* V = g_V + n*HW_;
    const float* K = g_K + n*HW_;

    for (int idx = tid; idx < 128*32; idx += 1024) {
        int row = idx >> 5, c4 = (idx & 31) * 4;
        *(float4*)&A[row*LDA + c4]  = *(const float4*)&Q[row*128 + c4];
        *(float4*)&Bm[row*LDA + c4] = *(const float4*)&V[row*128 + c4];
    }
    __syncthreads();

    const int g4 = lane >> 2;
    const int tg = lane & 3;
    const int r0 = wb*16 + g4;
    const int nt0 = wq*4;          // first n-tile of this warp's quarter

    float acc[4][4];
    #pragma unroll
    for (int j = 0; j < 4; j++)
        #pragma unroll
        for (int i = 0; i < 4; i++) acc[j][i] = 0.0f;

    // ---- Phase A: S = Q @ V^T (this warp's 4 n-tiles)
    #pragma unroll 1
    for (int k = 0; k < 16; k++) {
        const int kb = k*8 + tg;
        uint32_t ah[4], al[4];
        tf32_split(A[r0*LDA + kb],         ah[0], al[0]);
        tf32_split(A[(r0+8)*LDA + kb],     ah[1], al[1]);
        tf32_split(A[r0*LDA + kb + 4],     ah[2], al[2]);
        tf32_split(A[(r0+8)*LDA + kb + 4], ah[3], al[3]);
        #pragma unroll
        for (int j = 0; j < 4; j++) {
            const int gc = (nt0 + j)*8 + g4;
            uint32_t bh0, bl0, bh1, bl1;
            tf32_split(Bm[gc*LDA + kb],     bh0, bl0);
            tf32_split(Bm[gc*LDA + kb + 4], bh1, bl1);
            mma_tf32(acc[j], ah, bh0, bh1);
            mma_tf32(acc[j], al, bh0, bh1);
            mma_tf32(acc[j], ah, bl0, bl1);
        }
    }

    // ---- Softmax: partial max over this quarter, combine across 4 warps
    float m1 = -1e30f, m2 = -1e30f;
    #pragma unroll
    for (int j = 0; j < 4; j++) {
        m1 = fmaxf(m1, fmaxf(acc[j][0], acc[j][1]));
        m2 = fmaxf(m2, fmaxf(acc[j][2], acc[j][3]));
    }
    #pragma unroll
    for (int off = 1; off < 4; off <<= 1) {
        m1 = fmaxf(m1, __shfl_xor_sync(0xFFFFFFFFu, m1, off));
        m2 = fmaxf(m2, __shfl_xor_sync(0xFFFFFFFFu, m2, off));
    }
    if (tg == 0) {
        redM[wq*128 + r0]     = m1;
        redM[wq*128 + r0 + 8] = m2;
    }
    __syncthreads();   // phase-A reads done + partial maxes visible

    const float gm1 = fmaxf(fmaxf(redM[r0],       redM[128 + r0]),
                            fmaxf(redM[256 + r0], redM[384 + r0]));
    const float gm2 = fmaxf(fmaxf(redM[r0+8],       redM[128 + r0+8]),
                            fmaxf(redM[256 + r0+8], redM[384 + r0+8]));

    float s1 = 0.0f, s2 = 0.0f;
    #pragma unroll
    for (int j = 0; j < 4; j++) {
        acc[j][0] = __expf(acc[j][0] - gm1);
        acc[j][1] = __expf(acc[j][1] - gm1);
        acc[j][2] = __expf(acc[j][2] - gm2);
        acc[j][3] = __expf(acc[j][3] - gm2);
        s1 += acc[j][0] + acc[j][1];
        s2 += acc[j][2] + acc[j][3];
    }
    #pragma unroll
    for (int off = 1; off < 4; off <<= 1) {
        s1 += __shfl_xor_sync(0xFFFFFFFFu, s1, off);
        s2 += __shfl_xor_sync(0xFFFFFFFFu, s2, off);
    }
    if (tg == 0) {
        redS[wq*128 + r0]     = s1;
        redS[wq*128 + r0 + 8] = s2;
    }

    // Store unnormalized P into A (disjoint column quarters per warp)
    #pragma unroll
    for (int j = 0; j < 4; j++) {
        const int cb = (nt0 + j)*8 + 2*tg;
        *(float2*)&A[r0*LDA     + cb] = make_float2(acc[j][0], acc[j][1]);
        *(float2*)&A[(r0+8)*LDA + cb] = make_float2(acc[j][2], acc[j][3]);
    }
    // Stage K into Bm (V no longer needed)
    for (int idx = tid; idx < 128*32; idx += 1024) {
        int row = idx >> 5, c4 = (idx & 31) * 4;
        *(float4*)&Bm[row*LDA + c4] = *(const float4*)&K[row*128 + c4];
    }
    __syncthreads();   // P complete, K staged, partial sums visible

    const float inv1 = 1.0f / (redS[r0] + redS[128 + r0] +
                               redS[256 + r0] + redS[384 + r0]);
    const float inv2 = 1.0f / (redS[r0+8] + redS[128 + r0+8] +
                               redS[256 + r0+8] + redS[384 + r0+8]);

    // ---- Phase C: ctx = P @ K
    float oac[4][4];
    #pragma unroll
    for (int j = 0; j < 4; j++)
        #pragma unroll
        for (int i = 0; i < 4; i++) oac[j][i] = 0.0f;

    #pragma unroll 1
    for (int k = 0; k < 16; k++) {
        const int kb = k*8 + tg;
        uint32_t ah[4], al[4];
        tf32_split(A[r0*LDA + kb],         ah[0], al[0]);
        tf32_split(A[(r0+8)*LDA + kb],     ah[1], al[1]);
        tf32_split(A[r0*LDA + kb + 4],     ah[2], al[2]);
        tf32_split(A[(r0+8)*LDA + kb + 4], ah[3], al[3]);
        #pragma unroll
        for (int j = 0; j < 4; j++) {
            const int nc = (nt0 + j)*8 + g4;
            uint32_t bh0, bl0, bh1, bl1;
            tf32_split(Bm[kb*LDA + nc],     bh0, bl0);
            tf32_split(Bm[(kb+4)*LDA + nc], bh1, bl1);
            mma_tf32(oac[j], ah, bh0, bh1);
            mma_tf32(oac[j], al, bh0, bh1);
            mma_tf32(oac[j], ah, bl0, bl1);
        }
    }

    // Epilogue
    #pragma unroll
    for (int j = 0; j < 4; j++) {
        const int cb = (nt0 + j)*8 + 2*tg;
        *(float2*)&out[n*HW_ + r0*128 + cb] =
            make_float2(oac[j][0]*inv1, oac[j][1]*inv1);
        *(float2*)&out[n*HW_ + (r0+8)*128 + cb] =
            make_float2(oac[j][2]*inv2, oac[j][3]*inv2);
    }
}

// ---------------------------------------------------------------------------
extern "C" void kernel_launch(void* const* d_in, const int* in_sizes, int n_in,
                              void* d_out, int out_size)
{
    const float* x  = (const float*)d_in[0];
    const float* e  = (const float*)d_in[1];
    const float* W1 = (const float*)d_in[2];
    const float* b1 = (const float*)d_in[3];
    const float* W2 = (const float*)d_in[4];
    const float* b2 = (const float*)d_in[5];
    const float* W3 = (const float*)d_in[6];
    const float* b3 = (const float*)d_in[7];
    float* out = (float*)d_out;

    const int smem1 = (4*64*68 + 2*64*20 + 3*64) * (int)sizeof(float);
    cudaFuncSetAttribute(qvk_kernel, cudaFuncAttributeMaxDynamicSharedMemorySize, smem1);
    qvk_kernel<<<dim3(128, 16), 512, smem1>>>(x, e, W1, b1, W2, b2, W3, b3);

    const int smem2 = (2*128*LDA + 8*128) * (int)sizeof(float);
    cudaFuncSetAttribute(attn_kernel, cudaFuncAttributeMaxDynamicSharedMemorySize, smem2);
    attn_kernel<<<NTOT, 1024, smem2>>>(out);
}